// round 4
// baseline (speedup 1.0000x reference)
#include <cuda_runtime.h>
#include <mma.h>
#include <math.h>

using namespace nvcuda;

#define Bb 2
#define Cc 320
#define Nn 1024
#define NHh 8
#define DHh 40
#define Ll 2
#define EPS 1e-5f
#define EDGE_SCALE 0.17677669529663687f
#define ATT_SCALE  0.15811388300841897f

__device__ float g_node[Bb * Nn * Cc];
__device__ float g_qk2[Bb * Nn * 2 * Cc];
__device__ float g_edge[Bb * Nn * Nn];
__device__ float g_s[Bb * Cc];
__device__ float g_y[Bb * Nn * Cc];
__device__ float g_qkv[Bb * Nn * 3 * Cc];
__device__ float g_mz[Bb * NHh * Nn * 2];
__device__ float g_nodeout[Bb * Nn * Cc];

__device__ __forceinline__ float blockReduceSum(float v, float* sred) {
    #pragma unroll
    for (int o = 16; o > 0; o >>= 1) v += __shfl_xor_sync(0xffffffffu, v, o);
    int w = threadIdx.x >> 5;
    if ((threadIdx.x & 31) == 0) sred[w] = v;
    __syncthreads();
    int nw = blockDim.x >> 5;
    if (threadIdx.x < 32) {
        float x = (threadIdx.x < nw) ? sred[threadIdx.x] : 0.f;
        #pragma unroll
        for (int o = 16; o > 0; o >>= 1) x += __shfl_xor_sync(0xffffffffu, x, o);
        if (threadIdx.x == 0) sred[0] = x;
    }
    __syncthreads();
    float r = sred[0];
    __syncthreads();
    return r;
}

__device__ __forceinline__ float blockReduceMax(float v, float* sred) {
    #pragma unroll
    for (int o = 16; o > 0; o >>= 1) v = fmaxf(v, __shfl_xor_sync(0xffffffffu, v, o));
    int w = threadIdx.x >> 5;
    if ((threadIdx.x & 31) == 0) sred[w] = v;
    __syncthreads();
    int nw = blockDim.x >> 5;
    if (threadIdx.x < 32) {
        float x = (threadIdx.x < nw) ? sred[threadIdx.x] : -INFINITY;
        #pragma unroll
        for (int o = 16; o > 0; o >>= 1) x = fmaxf(x, __shfl_xor_sync(0xffffffffu, x, o));
        if (threadIdx.x == 0) sred[0] = x;
    }
    __syncthreads();
    float r = sred[0];
    __syncthreads();
    return r;
}

__global__ void transpose_in(const float* __restrict__ x) {
    __shared__ float tile[32][33];
    int b = blockIdx.z;
    int c0 = blockIdx.y * 32, n0 = blockIdx.x * 32;
    int tx = threadIdx.x, ty = threadIdx.y;
    tile[ty][tx] = x[(long)b * Cc * Nn + (long)(c0 + ty) * Nn + n0 + tx];
    __syncthreads();
    g_node[((long)b * Nn + n0 + ty) * Cc + c0 + tx] = tile[tx][ty];
}

__global__ void transpose_out(float* __restrict__ out) {
    __shared__ float tile[32][33];
    int b = blockIdx.z;
    int c0 = blockIdx.y * 32, n0 = blockIdx.x * 32;
    int tx = threadIdx.x, ty = threadIdx.y;
    tile[ty][tx] = g_node[((long)b * Nn + n0 + ty) * Cc + c0 + tx];
    __syncthreads();
    out[(long)b * Cc * Nn + (long)(c0 + ty) * Nn + n0 + tx] = tile[tx][ty];
}

// TF32 WMMA NT GEMM: C = alpha*A@W^T + bias. Block 128x64, K-tile 32.
__global__ void gemm_tf32(const float* __restrict__ A, const float* __restrict__ W,
                          const float* __restrict__ bias, float* __restrict__ C,
                          int M, int Ncols, int K, int lda, int ldw, int ldc,
                          long sA, long sW, long sC, float alpha) {
    __shared__ float sbuf[8704];
    float (*As)[36] = (float(*)[36])sbuf;
    float (*Ws)[36] = (float(*)[36])(sbuf + 128 * 36);
    int z = blockIdx.z;
    A += (long)z * sA; W += (long)z * sW; C += (long)z * sC;
    int bm = blockIdx.y * 128, bn = blockIdx.x * 64;
    int tid = threadIdx.x;
    int w = tid >> 5;
    int wm = w >> 1, wn = w & 1;
    wmma::fragment<wmma::accumulator, 16, 16, 8, float> c[2][2];
    #pragma unroll
    for (int i = 0; i < 2; i++)
        #pragma unroll
        for (int j = 0; j < 2; j++) wmma::fill_fragment(c[i][j], 0.f);
    for (int k0 = 0; k0 < K; k0 += 32) {
        #pragma unroll
        for (int i = 0; i < 4; i++) {
            int idx = tid + i * 256;
            int r = idx >> 3, c4 = (idx & 7) * 4;
            *(float4*)&As[r][c4] = *(const float4*)&A[(long)(bm + r) * lda + k0 + c4];
        }
        #pragma unroll
        for (int i = 0; i < 2; i++) {
            int idx = tid + i * 256;
            int r = idx >> 3, c4 = (idx & 7) * 4;
            *(float4*)&Ws[r][c4] = *(const float4*)&W[(long)(bn + r) * ldw + k0 + c4];
        }
        __syncthreads();
        #pragma unroll
        for (int kk = 0; kk < 4; kk++) {
            wmma::fragment<wmma::matrix_a, 16, 16, 8, wmma::precision::tf32, wmma::row_major> a[2];
            wmma::fragment<wmma::matrix_b, 16, 16, 8, wmma::precision::tf32, wmma::col_major> bf[2];
            #pragma unroll
            for (int i = 0; i < 2; i++) {
                wmma::load_matrix_sync(a[i], &As[wm * 32 + i * 16][kk * 8], 36);
                #pragma unroll
                for (int e = 0; e < a[i].num_elements; e++) a[i].x[e] = wmma::__float_to_tf32(a[i].x[e]);
            }
            #pragma unroll
            for (int j = 0; j < 2; j++) {
                wmma::load_matrix_sync(bf[j], &Ws[wn * 32 + j * 16][kk * 8], 36);
                #pragma unroll
                for (int e = 0; e < bf[j].num_elements; e++) bf[j].x[e] = wmma::__float_to_tf32(bf[j].x[e]);
            }
            #pragma unroll
            for (int i = 0; i < 2; i++)
                #pragma unroll
                for (int j = 0; j < 2; j++) wmma::mma_sync(c[i][j], a[i], bf[j], c[i][j]);
        }
        __syncthreads();
    }
    #pragma unroll
    for (int i = 0; i < 2; i++)
        #pragma unroll
        for (int j = 0; j < 2; j++) {
            #pragma unroll
            for (int e = 0; e < c[i][j].num_elements; e++) c[i][j].x[e] *= alpha;
            wmma::store_matrix_sync(&sbuf[(wm * 32 + i * 16) * 68 + wn * 32 + j * 16],
                                    c[i][j], 68, wmma::mem_row_major);
        }
    __syncthreads();
    #pragma unroll
    for (int i = 0; i < 8; i++) {
        int idx = tid + i * 256;
        int r = idx >> 4, c4 = (idx & 15) * 4;
        float4 v = *(float4*)&sbuf[r * 68 + c4];
        if (bias) {
            float4 bb = *(const float4*)&bias[bn + c4];
            v.x += bb.x; v.y += bb.y; v.z += bb.z; v.w += bb.w;
        }
        *(float4*)&C[(long)(bm + r) * ldc + bn + c4] = v;
    }
}

__global__ void edge_softmax(void) {
    __shared__ float sred[32];
    long row = blockIdx.x;
    float* p = g_edge + row * Nn;
    int tid = threadIdx.x;
    float r[4];
    float lmax = -INFINITY;
    #pragma unroll
    for (int i = 0; i < 4; i++) { r[i] = p[tid + i * 256]; lmax = fmaxf(lmax, r[i]); }
    float smax = blockReduceMax(lmax, sred);
    float lsum = 0.f;
    #pragma unroll
    for (int i = 0; i < 4; i++) { r[i] = __expf(r[i] - smax); lsum += r[i]; }
    float Z = blockReduceSum(lsum, sred);
    float inv = 1.f / Z;
    #pragma unroll
    for (int i = 0; i < 4; i++) p[tid + i * 256] = r[i] * inv;
}

__global__ void fcp_kernel(const float* __restrict__ da, const float* __restrict__ fw,
                           const float* __restrict__ fb) {
    __shared__ float t[64];
    int b = blockIdx.x;
    int tid = threadIdx.x;
    if (tid < 64) {
        float s = 0.f;
        #pragma unroll
        for (int a = 0; a < 16; a++) s += da[(long)b * 16 * 64 + a * 64 + tid];
        t[tid] = s;
    }
    __syncthreads();
    float s = 16.f * fb[tid];
    #pragma unroll
    for (int e = 0; e < 64; e++) s += t[e] * fw[tid * 64 + e];
    g_s[b * Cc + tid] = s;
}

__global__ void norm_kernel(const float* __restrict__ g1, const float* __restrict__ b1,
                            const float* __restrict__ g2, const float* __restrict__ b2) {
    __shared__ float sred[32];
    int bn = blockIdx.x;
    int b = bn >> 10, n = bn & 1023;
    int c = threadIdx.x;
    float x = g_node[(long)bn * Cc + c];
    float mean = blockReduceSum(x, sred) * (1.f / Cc);
    float d = x - mean;
    float var = blockReduceSum(d * d, sred) * (1.f / Cc);
    float nt = d * rsqrtf(var + EPS) * g1[c] + b1[c];
    float diag = g_edge[(long)b * Nn * Nn + (long)n * Nn + n];
    float v2 = diag * nt * g_s[b * Cc + c] + nt;
    float mean2 = blockReduceSum(v2, sred) * (1.f / Cc);
    float dd = v2 - mean2;
    float var2 = blockReduceSum(dd * dd, sred) * (1.f / Cc);
    g_y[(long)bn * Cc + c] = dd * rsqrtf(var2 + EPS) * g2[c] + b2[c];
}

// ---- pass 1: per-row softmax stats (M, 1/Z). grid(8, NHh, Bb), 256 thr ----
__global__ void attn_stats(const float* __restrict__ exp_w, const float* __restrict__ exp_b) {
    extern __shared__ float sm[];
    float* Qs = sm;            // [128][44]
    float* Ks = sm + 5632;     // [64][44]
    float* Ss = sm + 8448;     // [8][16][68]
    float* es = sm + 17152;    // [128][68]
    int n0 = blockIdx.x * 128;
    int h = blockIdx.y, b = blockIdx.z;
    int tid = threadIdx.x;
    int w = tid >> 5, lane = tid & 31;
    const float* qkv = g_qkv + (long)b * Nn * 960;
    const float* ep = g_edge + (long)b * Nn * Nn;
    for (int i = tid; i < 1280; i += 256) {
        int r = i / 10, d4 = (i % 10) * 4;
        *(float4*)&Qs[r * 44 + d4] = *(const float4*)&qkv[(long)(n0 + r) * 960 + h * 40 + d4];
    }
    float ew = exp_w[h], eb = exp_b[h];
    int row16 = lane >> 1, bc = (lane & 1) * 32;
    int grow = w * 16 + row16;
    float mr = -INFINITY, zr = 0.f;
    for (int m0 = 0; m0 < Nn; m0 += 64) {
        for (int i = tid; i < 640; i += 256) {
            int r = i / 10, d4 = (i % 10) * 4;
            *(float4*)&Ks[r * 44 + d4] = *(const float4*)&qkv[(long)(m0 + r) * 960 + 320 + h * 40 + d4];
        }
        for (int i = tid; i < 2048; i += 256) {
            int r = i >> 4, c4 = (i & 15) * 4;
            *(float4*)&es[r * 68 + c4] = *(const float4*)&ep[(long)(n0 + r) * Nn + m0 + c4];
        }
        __syncthreads();
        {
            wmma::fragment<wmma::accumulator, 16, 16, 8, float> c[4];
            #pragma unroll
            for (int j = 0; j < 4; j++) wmma::fill_fragment(c[j], 0.f);
            #pragma unroll
            for (int kk = 0; kk < 5; kk++) {
                wmma::fragment<wmma::matrix_a, 16, 16, 8, wmma::precision::tf32, wmma::row_major> a;
                wmma::load_matrix_sync(a, &Qs[(w * 16) * 44 + kk * 8], 44);
                #pragma unroll
                for (int e = 0; e < a.num_elements; e++) a.x[e] = wmma::__float_to_tf32(a.x[e]);
                #pragma unroll
                for (int j = 0; j < 4; j++) {
                    wmma::fragment<wmma::matrix_b, 16, 16, 8, wmma::precision::tf32, wmma::col_major> bf;
                    wmma::load_matrix_sync(bf, &Ks[(j * 16) * 44 + kk * 8], 44);
                    #pragma unroll
                    for (int e = 0; e < bf.num_elements; e++) bf.x[e] = wmma::__float_to_tf32(bf.x[e]);
                    wmma::mma_sync(c[j], a, bf, c[j]);
                }
            }
            #pragma unroll
            for (int j = 0; j < 4; j++)
                wmma::store_matrix_sync(&Ss[w * 1088 + j * 16], c[j], 68, wmma::mem_row_major);
        }
        __syncthreads();
        #pragma unroll
        for (int j = 0; j < 32; j++) {
            int col = bc + j;
            float r = Ss[w * 1088 + row16 * 68 + col] * ATT_SCALE + es[grow * 68 + col] * ew + eb;
            if (r > mr) { float f = __expf(mr - r); zr = zr * f + 1.f; mr = r; }
            else zr += __expf(r - mr);
        }
        __syncthreads();
    }
    float mo = __shfl_xor_sync(0xffffffffu, mr, 1);
    float zo = __shfl_xor_sync(0xffffffffu, zr, 1);
    float nm = fmaxf(mr, mo);
    float Z = zr * __expf(mr - nm) + zo * __expf(mo - nm);
    if ((lane & 1) == 0) {
        long o = (((long)b * NHh + h) * Nn + n0 + grow) * 2;
        g_mz[o] = nm;
        g_mz[o + 1] = 1.f / Z;
    }
}

__device__ __forceinline__ unsigned f2tf(float x) {
    return __float_as_uint(wmma::__float_to_tf32(x));
}
__device__ __forceinline__ void mma8(float* c, const unsigned* a, const unsigned* b) {
    asm volatile("mma.sync.aligned.m16n8k8.row.col.f32.tf32.tf32.f32 "
                 "{%0,%1,%2,%3}, {%4,%5,%6,%7}, {%8,%9}, {%0,%1,%2,%3};\n"
                 : "+f"(c[0]), "+f"(c[1]), "+f"(c[2]), "+f"(c[3])
                 : "r"(a[0]), "r"(a[1]), "r"(a[2]), "r"(a[3]), "r"(b[0]), "r"(b[1]));
}

// ---- pass 2: fused attention. grid(64, Bb), 256 thr, warp = head ---------
__global__ void attn_fused(const float* __restrict__ exp_w, const float* __restrict__ exp_b,
                           const float* __restrict__ red_w, const float* __restrict__ red_b) {
    extern __shared__ float sm[];
    float* Qs    = sm;           // [8][16][44]
    float* Ss    = sm + 5632;    // [8][16][68] scores->probs->AV out
    float* Ts    = sm + 14336;   // [8][16][68] rw*(a+r)
    float* KV    = sm + 23040;   // [8][64][44] K then V
    float* es    = sm + 45568;   // [16][68]
    float* mzs   = sm + 46656;   // [8][16][2]
    float* wsums = sm + 46912;   // [16]
    int n0 = blockIdx.x * 16;
    int b = blockIdx.y;
    int tid = threadIdx.x;
    int h = tid >> 5, lane = tid & 31;
    const float* qkv = g_qkv + (long)b * Nn * 960;
    float* ep = g_edge + (long)b * Nn * Nn;
    for (int i = tid; i < 1280; i += 256) {
        int r = i / 80, rem = i % 80, hh = rem / 10, d4 = (rem % 10) * 4;
        *(float4*)&Qs[hh * 704 + r * 44 + d4] =
            *(const float4*)&qkv[(long)(n0 + r) * 960 + hh * 40 + d4];
    }
    {
        int hh = tid >> 5, r = (tid >> 1) & 15, cp = tid & 1;
        mzs[hh * 32 + r * 2 + cp] = g_mz[(((long)b * NHh + hh) * Nn + n0 + r) * 2 + cp];
    }
    float ew = exp_w[h], eb2 = exp_b[h], rw = red_w[h], rb = red_b[0];
    float acc[5][4];
    #pragma unroll
    for (int nb = 0; nb < 5; nb++)
        #pragma unroll
        for (int q = 0; q < 4; q++) acc[nb][q] = 0.f;
    float me = -INFINITY, ze = 0.f, se = 0.f;
    int row16 = lane >> 1, bc = (lane & 1) * 32;
    int erow = tid >> 4, ecol = tid & 15;
    for (int m0 = 0; m0 < Nn; m0 += 64) {
        {
            int r = tid >> 4, c4 = (tid & 15) * 4;
            *(float4*)&es[r * 68 + c4] = *(const float4*)&ep[(long)(n0 + r) * Nn + m0 + c4];
        }
        for (int i = lane; i < 640; i += 32) {
            int r = i / 10, d4 = (i % 10) * 4;
            *(float4*)&KV[h * 2816 + r * 44 + d4] =
                *(const float4*)&qkv[(long)(m0 + r) * 960 + 320 + h * 40 + d4];
        }
        __syncthreads();
        {
            wmma::fragment<wmma::accumulator, 16, 16, 8, float> c[4];
            #pragma unroll
            for (int j = 0; j < 4; j++) wmma::fill_fragment(c[j], 0.f);
            #pragma unroll
            for (int kk = 0; kk < 5; kk++) {
                wmma::fragment<wmma::matrix_a, 16, 16, 8, wmma::precision::tf32, wmma::row_major> a;
                wmma::load_matrix_sync(a, &Qs[h * 704 + kk * 8], 44);
                #pragma unroll
                for (int e = 0; e < a.num_elements; e++) a.x[e] = wmma::__float_to_tf32(a.x[e]);
                #pragma unroll
                for (int j = 0; j < 4; j++) {
                    wmma::fragment<wmma::matrix_b, 16, 16, 8, wmma::precision::tf32, wmma::col_major> bf;
                    wmma::load_matrix_sync(bf, &KV[h * 2816 + j * 16 * 44 + kk * 8], 44);
                    #pragma unroll
                    for (int e = 0; e < bf.num_elements; e++) bf.x[e] = wmma::__float_to_tf32(bf.x[e]);
                    wmma::mma_sync(c[j], a, bf, c[j]);
                }
            }
            #pragma unroll
            for (int j = 0; j < 4; j++)
                wmma::store_matrix_sync(&Ss[h * 1088 + j * 16], c[j], 68, wmma::mem_row_major);
        }
        __syncthreads();
        for (int i = lane; i < 640; i += 32) {  // V overwrites K (warp-local use)
            int r = i / 10, d4 = (i % 10) * 4;
            *(float4*)&KV[h * 2816 + r * 44 + d4] =
                *(const float4*)&qkv[(long)(m0 + r) * 960 + 640 + h * 40 + d4];
        }
        {
            float M = mzs[h * 32 + row16 * 2], iZ = mzs[h * 32 + row16 * 2 + 1];
            #pragma unroll
            for (int j = 0; j < 32; j++) {
                int col = bc + j;
                float raw = Ss[h * 1088 + row16 * 68 + col];
                float r = raw * ATT_SCALE + es[row16 * 68 + col] * ew + eb2;
                float a = __expf(r - M) * iZ;
                Ss[h * 1088 + row16 * 68 + col] = a;
                Ts[h * 1088 + row16 * 68 + col] = rw * (a + r);
            }
        }
        __syncthreads();
        #pragma unroll
        for (int k = 0; k < 4; k++) {
            int col = ecol + k * 16;
            float en = rb;
            #pragma unroll
            for (int hh = 0; hh < 8; hh++) en += Ts[hh * 1088 + erow * 68 + col];
            ep[(long)(n0 + erow) * Nn + m0 + col] = es[erow * 68 + col] + en;
            if (en > me) { float f = __expf(me - en); ze = ze * f + 1.f; se = se * f + en; me = en; }
            else { float f = __expf(en - me); ze += f; se += f * en; }
        }
        #pragma unroll
        for (int kk = 0; kk < 8; kk++) {
            unsigned afr[4];
            int ar = lane >> 2, ak = kk * 8 + (lane & 3);
            afr[0] = f2tf(Ss[h * 1088 + ar * 68 + ak]);
            afr[1] = f2tf(Ss[h * 1088 + (ar + 8) * 68 + ak]);
            afr[2] = f2tf(Ss[h * 1088 + ar * 68 + ak + 4]);
            afr[3] = f2tf(Ss[h * 1088 + (ar + 8) * 68 + ak + 4]);
            #pragma unroll
            for (int nb = 0; nb < 5; nb++) {
                unsigned bfr[2];
                int bn = nb * 8 + (lane >> 2);
                bfr[0] = f2tf(KV[h * 2816 + ak * 44 + bn]);
                bfr[1] = f2tf(KV[h * 2816 + (ak + 4) * 44 + bn]);
                mma8(acc[nb], afr, bfr);
            }
        }
        __syncthreads();
    }
    #pragma unroll
    for (int off = 8; off > 0; off >>= 1) {
        float mo = __shfl_xor_sync(0xffffffffu, me, off);
        float zo = __shfl_xor_sync(0xffffffffu, ze, off);
        float so = __shfl_xor_sync(0xffffffffu, se, off);
        float nm = fmaxf(me, mo);
        float f1 = __expf(me - nm), f2 = __expf(mo - nm);
        ze = ze * f1 + zo * f2;
        se = se * f1 + so * f2;
        me = nm;
    }
    if (ecol == 0) wsums[erow] = se / ze;
    #pragma unroll
    for (int nb = 0; nb < 5; nb++) {
        int r = lane >> 2, c = nb * 8 + 2 * (lane & 3);
        Ss[h * 1088 + r * 68 + c]           = acc[nb][0];
        Ss[h * 1088 + r * 68 + c + 1]       = acc[nb][1];
        Ss[h * 1088 + (r + 8) * 68 + c]     = acc[nb][2];
        Ss[h * 1088 + (r + 8) * 68 + c + 1] = acc[nb][3];
    }
    __syncthreads();
    for (int i = tid; i < 1280; i += 256) {
        int r = i / 80, rem = i % 80, hh = rem / 10, d4 = (rem % 10) * 4;
        float w = wsums[r];
        float4 v = *(float4*)&Ss[hh * 1088 + r * 68 + d4];
        v.x += w; v.y += w; v.z += w; v.w += w;
        *(float4*)&g_nodeout[((long)b * Nn + n0 + r) * 320 + hh * 40 + d4] = v;
    }
}

static float* sym(const void* s) {
    void* p = nullptr;
    cudaGetSymbolAddress(&p, s);
    return (float*)p;
}

#define SMEM_STATS (25856 * 4)
#define SMEM_FUSED (46928 * 4)

extern "C" void kernel_launch(void* const* d_in, const int* in_sizes, int n_in,
                              void* d_out, int out_size) {
    const float* x        = (const float*)d_in[0];
    const float* da_prior = (const float*)d_in[1];
    const float* qk_w     = (const float*)d_in[2];
    const float* fcp_w    = (const float*)d_in[3];
    const float* fcp_b    = (const float*)d_in[4];
    const float* ln1_g    = (const float*)d_in[5];
    const float* ln1_b    = (const float*)d_in[6];
    const float* gln_g    = (const float*)d_in[7];
    const float* gln_b    = (const float*)d_in[8];
    const float* qkv_w    = (const float*)d_in[9];
    const float* qkv_b    = (const float*)d_in[10];
    const float* proj_w   = (const float*)d_in[11];
    const float* proj_b   = (const float*)d_in[12];
    const float* exp_w    = (const float*)d_in[13];
    const float* exp_b    = (const float*)d_in[14];
    const float* red_w    = (const float*)d_in[15];
    const float* red_b    = (const float*)d_in[16];
    float* out = (float*)d_out;

    float* p_node    = sym(g_node);
    float* p_qk2     = sym(g_qk2);
    float* p_edge    = sym(g_edge);
    float* p_y       = sym(g_y);
    float* p_qkv     = sym(g_qkv);
    float* p_nodeout = sym(g_nodeout);

    cudaFuncSetAttribute(attn_stats, cudaFuncAttributeMaxDynamicSharedMemorySize, SMEM_STATS);
    cudaFuncSetAttribute(attn_fused, cudaFuncAttributeMaxDynamicSharedMemorySize, SMEM_FUSED);

    transpose_in<<<dim3(32, 10, Bb), dim3(32, 32)>>>(x);
    gemm_tf32<<<dim3(10, 16, 1), 256>>>(p_node, qk_w, nullptr, p_qk2,
                                        Bb * Nn, 2 * Cc, Cc, Cc, Cc, 2 * Cc, 0, 0, 0, 1.f);
    gemm_tf32<<<dim3(16, 8, Bb), 256>>>(p_qk2, p_qk2 + Cc, nullptr, p_edge,
                                        Nn, Nn, Cc, 2 * Cc, 2 * Cc, Nn,
                                        (long)Nn * 2 * Cc, (long)Nn * 2 * Cc, (long)Nn * Nn,
                                        EDGE_SCALE);
    edge_softmax<<<Bb * Nn, 256>>>();
    fcp_kernel<<<Bb, Cc>>>(da_prior, fcp_w, fcp_b);

    for (int l = 0; l < Ll; l++) {
        norm_kernel<<<Bb * Nn, Cc>>>(ln1_g + l * Cc, ln1_b + l * Cc,
                                     gln_g + l * Cc, gln_b + l * Cc);
        gemm_tf32<<<dim3(15, 16, 1), 256>>>(p_y, qkv_w + (long)l * 3 * Cc * Cc,
                                            qkv_b + l * 3 * Cc, p_qkv,
                                            Bb * Nn, 3 * Cc, Cc, Cc, Cc, 3 * Cc, 0, 0, 0, 1.f);
        attn_stats<<<dim3(8, NHh, Bb), 256, SMEM_STATS>>>(exp_w + l * NHh, exp_b + l * NHh);
        attn_fused<<<dim3(64, Bb), 256, SMEM_FUSED>>>(exp_w + l * NHh, exp_b + l * NHh,
                                                      red_w + l * NHh, red_b + l);
        gemm_tf32<<<dim3(5, 16, 1), 256>>>(p_nodeout, proj_w + (long)l * Cc * Cc,
                                           proj_b + l * Cc, p_node,
                                           Bb * Nn, Cc, Cc, Cc, Cc, Cc, 0, 0, 0, 1.f);
    }
    transpose_out<<<dim3(32, 10, Bb), dim3(32, 32)>>>(out);
}

// round 5
// speedup vs baseline: 1.3817x; 1.3817x over previous
#include <cuda_runtime.h>
#include <mma.h>
#include <math.h>

using namespace nvcuda;

#define Bb 2
#define Cc 320
#define Nn 1024
#define NHh 8
#define DHh 40
#define Ll 2
#define EPS 1e-5f
#define EDGE_SCALE 0.17677669529663687f
#define ATT_SCALE  0.15811388300841897f

__device__ float g_node[Bb * Nn * Cc];
__device__ float g_qk2[Bb * Nn * 2 * Cc];
__device__ float g_edge[Bb * Nn * Nn];
__device__ float g_s[Bb * Cc];
__device__ float g_y[Bb * Nn * Cc];
__device__ float g_qkv[Bb * Nn * 3 * Cc];
__device__ float g_attn[Bb * NHh * Nn * Nn];
__device__ float g_wsum[Bb * Nn];
__device__ float g_nodeout[Bb * Nn * Cc];

__device__ __forceinline__ float blockReduceSum(float v, float* sred) {
    #pragma unroll
    for (int o = 16; o > 0; o >>= 1) v += __shfl_xor_sync(0xffffffffu, v, o);
    int w = threadIdx.x >> 5;
    if ((threadIdx.x & 31) == 0) sred[w] = v;
    __syncthreads();
    int nw = blockDim.x >> 5;
    if (threadIdx.x < 32) {
        float x = (threadIdx.x < nw) ? sred[threadIdx.x] : 0.f;
        #pragma unroll
        for (int o = 16; o > 0; o >>= 1) x += __shfl_xor_sync(0xffffffffu, x, o);
        if (threadIdx.x == 0) sred[0] = x;
    }
    __syncthreads();
    float r = sred[0];
    __syncthreads();
    return r;
}

__device__ __forceinline__ float blockReduceMax(float v, float* sred) {
    #pragma unroll
    for (int o = 16; o > 0; o >>= 1) v = fmaxf(v, __shfl_xor_sync(0xffffffffu, v, o));
    int w = threadIdx.x >> 5;
    if ((threadIdx.x & 31) == 0) sred[w] = v;
    __syncthreads();
    int nw = blockDim.x >> 5;
    if (threadIdx.x < 32) {
        float x = (threadIdx.x < nw) ? sred[threadIdx.x] : -INFINITY;
        #pragma unroll
        for (int o = 16; o > 0; o >>= 1) x = fmaxf(x, __shfl_xor_sync(0xffffffffu, x, o));
        if (threadIdx.x == 0) sred[0] = x;
    }
    __syncthreads();
    float r = sred[0];
    __syncthreads();
    return r;
}

__global__ void transpose_in(const float* __restrict__ x) {
    __shared__ float tile[32][33];
    int b = blockIdx.z;
    int c0 = blockIdx.y * 32, n0 = blockIdx.x * 32;
    int tx = threadIdx.x, ty = threadIdx.y;
    tile[ty][tx] = x[(long)b * Cc * Nn + (long)(c0 + ty) * Nn + n0 + tx];
    __syncthreads();
    g_node[((long)b * Nn + n0 + ty) * Cc + c0 + tx] = tile[tx][ty];
}

__global__ void transpose_out(float* __restrict__ out) {
    __shared__ float tile[32][33];
    int b = blockIdx.z;
    int c0 = blockIdx.y * 32, n0 = blockIdx.x * 32;
    int tx = threadIdx.x, ty = threadIdx.y;
    tile[ty][tx] = g_node[((long)b * Nn + n0 + ty) * Cc + c0 + tx];
    __syncthreads();
    out[(long)b * Cc * Nn + (long)(c0 + ty) * Nn + n0 + tx] = tile[tx][ty];
}

// TF32 WMMA NT GEMM: C = alpha*A@W^T + bias. Block 128x64, K-tile 32.
__global__ void gemm_tf32(const float* __restrict__ A, const float* __restrict__ W,
                          const float* __restrict__ bias, float* __restrict__ C,
                          int M, int Ncols, int K, int lda, int ldw, int ldc,
                          long sA, long sW, long sC, float alpha) {
    __shared__ float sbuf[8704];
    float (*As)[36] = (float(*)[36])sbuf;
    float (*Ws)[36] = (float(*)[36])(sbuf + 128 * 36);
    int z = blockIdx.z;
    A += (long)z * sA; W += (long)z * sW; C += (long)z * sC;
    int bm = blockIdx.y * 128, bn = blockIdx.x * 64;
    int tid = threadIdx.x;
    int w = tid >> 5;
    int wm = w >> 1, wn = w & 1;
    wmma::fragment<wmma::accumulator, 16, 16, 8, float> c[2][2];
    #pragma unroll
    for (int i = 0; i < 2; i++)
        #pragma unroll
        for (int j = 0; j < 2; j++) wmma::fill_fragment(c[i][j], 0.f);
    for (int k0 = 0; k0 < K; k0 += 32) {
        #pragma unroll
        for (int i = 0; i < 4; i++) {
            int idx = tid + i * 256;
            int r = idx >> 3, c4 = (idx & 7) * 4;
            *(float4*)&As[r][c4] = *(const float4*)&A[(long)(bm + r) * lda + k0 + c4];
        }
        #pragma unroll
        for (int i = 0; i < 2; i++) {
            int idx = tid + i * 256;
            int r = idx >> 3, c4 = (idx & 7) * 4;
            *(float4*)&Ws[r][c4] = *(const float4*)&W[(long)(bn + r) * ldw + k0 + c4];
        }
        __syncthreads();
        #pragma unroll
        for (int kk = 0; kk < 4; kk++) {
            wmma::fragment<wmma::matrix_a, 16, 16, 8, wmma::precision::tf32, wmma::row_major> a[2];
            wmma::fragment<wmma::matrix_b, 16, 16, 8, wmma::precision::tf32, wmma::col_major> bf[2];
            #pragma unroll
            for (int i = 0; i < 2; i++) {
                wmma::load_matrix_sync(a[i], &As[wm * 32 + i * 16][kk * 8], 36);
                #pragma unroll
                for (int e = 0; e < a[i].num_elements; e++) a[i].x[e] = wmma::__float_to_tf32(a[i].x[e]);
            }
            #pragma unroll
            for (int j = 0; j < 2; j++) {
                wmma::load_matrix_sync(bf[j], &Ws[wn * 32 + j * 16][kk * 8], 36);
                #pragma unroll
                for (int e = 0; e < bf[j].num_elements; e++) bf[j].x[e] = wmma::__float_to_tf32(bf[j].x[e]);
            }
            #pragma unroll
            for (int i = 0; i < 2; i++)
                #pragma unroll
                for (int j = 0; j < 2; j++) wmma::mma_sync(c[i][j], a[i], bf[j], c[i][j]);
        }
        __syncthreads();
    }
    #pragma unroll
    for (int i = 0; i < 2; i++)
        #pragma unroll
        for (int j = 0; j < 2; j++) {
            #pragma unroll
            for (int e = 0; e < c[i][j].num_elements; e++) c[i][j].x[e] *= alpha;
            wmma::store_matrix_sync(&sbuf[(wm * 32 + i * 16) * 68 + wn * 32 + j * 16],
                                    c[i][j], 68, wmma::mem_row_major);
        }
    __syncthreads();
    #pragma unroll
    for (int i = 0; i < 8; i++) {
        int idx = tid + i * 256;
        int r = idx >> 4, c4 = (idx & 15) * 4;
        float4 v = *(float4*)&sbuf[r * 68 + c4];
        if (bias) {
            float4 bb = *(const float4*)&bias[bn + c4];
            v.x += bb.x; v.y += bb.y; v.z += bb.z; v.w += bb.w;
        }
        *(float4*)&C[(long)(bm + r) * ldc + bn + c4] = v;
    }
}

// row softmax (in-place) for edge, vectorized
__global__ void edge_softmax(void) {
    __shared__ float sred[32];
    long row = blockIdx.x;
    float* p = g_edge + row * Nn;
    int tid = threadIdx.x;  // 256
    float4 r = *(float4*)&p[tid * 4];
    float lmax = fmaxf(fmaxf(r.x, r.y), fmaxf(r.z, r.w));
    float smax = blockReduceMax(lmax, sred);
    r.x = __expf(r.x - smax); r.y = __expf(r.y - smax);
    r.z = __expf(r.z - smax); r.w = __expf(r.w - smax);
    float Z = blockReduceSum(r.x + r.y + r.z + r.w, sred);
    float inv = 1.f / Z;
    r.x *= inv; r.y *= inv; r.z *= inv; r.w *= inv;
    *(float4*)&p[tid * 4] = r;
}

__global__ void fcp_kernel(const float* __restrict__ da, const float* __restrict__ fw,
                           const float* __restrict__ fb) {
    __shared__ float t[64];
    int b = blockIdx.x;
    int tid = threadIdx.x;
    if (tid < 64) {
        float s = 0.f;
        #pragma unroll
        for (int a = 0; a < 16; a++) s += da[(long)b * 16 * 64 + a * 64 + tid];
        t[tid] = s;
    }
    __syncthreads();
    float s = 16.f * fb[tid];
    #pragma unroll
    for (int e = 0; e < 64; e++) s += t[e] * fw[tid * 64 + e];
    g_s[b * Cc + tid] = s;
}

__global__ void norm_kernel(const float* __restrict__ g1, const float* __restrict__ b1,
                            const float* __restrict__ g2, const float* __restrict__ b2) {
    __shared__ float sred[32];
    int bn = blockIdx.x;
    int b = bn >> 10, n = bn & 1023;
    int c = threadIdx.x;
    float x = g_node[(long)bn * Cc + c];
    float mean = blockReduceSum(x, sred) * (1.f / Cc);
    float d = x - mean;
    float var = blockReduceSum(d * d, sred) * (1.f / Cc);
    float nt = d * rsqrtf(var + EPS) * g1[c] + b1[c];
    float diag = g_edge[(long)b * Nn * Nn + (long)n * Nn + n];
    float v2 = diag * nt * g_s[b * Cc + c] + nt;
    float mean2 = blockReduceSum(v2, sred) * (1.f / Cc);
    float dd = v2 - mean2;
    float var2 = blockReduceSum(dd * dd, sred) * (1.f / Cc);
    g_y[(long)bn * Cc + c] = dd * rsqrtf(var2 + EPS) * g2[c] + b2[c];
}

// attn scores (TF32 WMMA): S = QK^T*scale + edge*ew + eb
__global__ void attn_score_tf32(const float* __restrict__ exp_w, const float* __restrict__ exp_b) {
    __shared__ float sb[5632];
    float (*Qs)[44] = (float(*)[44])sb;
    float (*Ks)[44] = (float(*)[44])(sb + 64 * 44);
    int bh = blockIdx.z;
    int b = bh >> 3, h = bh & 7;
    int n0 = blockIdx.y * 64, m0 = blockIdx.x * 64;
    const float* Qb = g_qkv + (long)b * Nn * 960 + h * DHh;
    const float* Kb = Qb + Cc;
    int tid = threadIdx.x;
    for (int idx = tid; idx < 640; idx += 256) {
        int r = idx / 10, c4 = (idx % 10) * 4;
        *(float4*)&Qs[r][c4] = *(const float4*)&Qb[(long)(n0 + r) * 960 + c4];
        *(float4*)&Ks[r][c4] = *(const float4*)&Kb[(long)(m0 + r) * 960 + c4];
    }
    __syncthreads();
    int w = tid >> 5, wr = w >> 1, wc = w & 1;
    wmma::fragment<wmma::accumulator, 16, 16, 8, float> c[2];
    wmma::fill_fragment(c[0], 0.f);
    wmma::fill_fragment(c[1], 0.f);
    #pragma unroll
    for (int kk = 0; kk < 5; kk++) {
        wmma::fragment<wmma::matrix_a, 16, 16, 8, wmma::precision::tf32, wmma::row_major> a;
        wmma::load_matrix_sync(a, &Qs[wr * 16][kk * 8], 44);
        #pragma unroll
        for (int e = 0; e < a.num_elements; e++) a.x[e] = wmma::__float_to_tf32(a.x[e]);
        #pragma unroll
        for (int j = 0; j < 2; j++) {
            wmma::fragment<wmma::matrix_b, 16, 16, 8, wmma::precision::tf32, wmma::col_major> bf;
            wmma::load_matrix_sync(bf, &Ks[wc * 32 + j * 16][kk * 8], 44);
            #pragma unroll
            for (int e = 0; e < bf.num_elements; e++) bf.x[e] = wmma::__float_to_tf32(bf.x[e]);
            wmma::mma_sync(c[j], a, bf, c[j]);
        }
    }
    __syncthreads();
    #pragma unroll
    for (int j = 0; j < 2; j++) {
        #pragma unroll
        for (int e = 0; e < c[j].num_elements; e++) c[j].x[e] *= ATT_SCALE;
        wmma::store_matrix_sync(&sb[(wr * 16) * 68 + wc * 32 + j * 16], c[j], 68,
                                wmma::mem_row_major);
    }
    __syncthreads();
    float ew = exp_w[h], eb = exp_b[h];
    const float* ep = g_edge + (long)b * Nn * Nn;
    float* op = g_attn + ((long)b * NHh + h) * Nn * Nn;
    #pragma unroll
    for (int i = 0; i < 4; i++) {
        int idx = tid + i * 256;
        int r = idx >> 4, c4 = (idx & 15) * 4;
        float4 s = *(float4*)&sb[r * 68 + c4];
        float4 e = *(const float4*)&ep[(long)(n0 + r) * Nn + m0 + c4];
        s.x += e.x * ew + eb; s.y += e.y * ew + eb;
        s.z += e.z * ew + eb; s.w += e.w * ew + eb;
        *(float4*)&op[(long)(n0 + r) * Nn + m0 + c4] = s;
    }
}

// (m,z,s) online-softmax triple merge
__device__ __forceinline__ void mergeTriple(float& m, float& z, float& s,
                                            float mo, float zo, float so) {
    float nm = fmaxf(m, mo);
    float f1 = __expf(m - nm), f2 = __expf(mo - nm);
    z = z * f1 + zo * f2;
    s = s * f1 + so * f2;
    m = nm;
}

// warp-per-head softmax + edge_new + edge update + wsum. 2 barriers total.
__global__ void softmax_ednew(const float* __restrict__ red_w, const float* __restrict__ red_b) {
    __shared__ float Ts[NHh][Nn];   // 32 KB
    __shared__ float red3[24];
    int bn = blockIdx.x;
    int b = bn >> 10, n = bn & 1023;
    int tid = threadIdx.x;          // 256 = 8 warps
    int w = tid >> 5, lane = tid & 31;
    float* Ab = g_attn + (((long)b * NHh + w) * Nn + n) * Nn;
    float rw = red_w[w];

    // phase 1: warp w handles head w's full row in registers
    float4 r[8], e[8];
    #pragma unroll
    for (int k = 0; k < 8; k++) r[k] = *(float4*)&Ab[lane * 4 + k * 128];
    float M = -INFINITY;
    #pragma unroll
    for (int k = 0; k < 8; k++)
        M = fmaxf(M, fmaxf(fmaxf(r[k].x, r[k].y), fmaxf(r[k].z, r[k].w)));
    #pragma unroll
    for (int o = 16; o > 0; o >>= 1) M = fmaxf(M, __shfl_xor_sync(0xffffffffu, M, o));
    float Z = 0.f;
    #pragma unroll
    for (int k = 0; k < 8; k++) {
        e[k].x = __expf(r[k].x - M); e[k].y = __expf(r[k].y - M);
        e[k].z = __expf(r[k].z - M); e[k].w = __expf(r[k].w - M);
        Z += e[k].x + e[k].y + e[k].z + e[k].w;
    }
    #pragma unroll
    for (int o = 16; o > 0; o >>= 1) Z += __shfl_xor_sync(0xffffffffu, Z, o);
    float inv = 1.f / Z;
    #pragma unroll
    for (int k = 0; k < 8; k++) {
        float4 a;
        a.x = e[k].x * inv; a.y = e[k].y * inv; a.z = e[k].z * inv; a.w = e[k].w * inv;
        *(float4*)&Ab[lane * 4 + k * 128] = a;   // probs in place (for AV)
        float4 t;
        t.x = rw * (a.x + r[k].x); t.y = rw * (a.y + r[k].y);
        t.z = rw * (a.z + r[k].z); t.w = rw * (a.w + r[k].w);
        *(float4*)&Ts[w][lane * 4 + k * 128] = t;
    }
    __syncthreads();

    // phase 2: cross-head sum at cols tid*4..tid*4+3
    float rb = red_b[0];
    float4 en = {rb, rb, rb, rb};
    #pragma unroll
    for (int h = 0; h < NHh; h++) {
        float4 t = *(float4*)&Ts[h][tid * 4];
        en.x += t.x; en.y += t.y; en.z += t.z; en.w += t.w;
    }
    float* ep = g_edge + (long)b * Nn * Nn + (long)n * Nn;
    float4 ec = *(float4*)&ep[tid * 4];
    ec.x += en.x; ec.y += en.y; ec.z += en.z; ec.w += en.w;
    *(float4*)&ep[tid * 4] = ec;
    // online (m,z,s) over my 4 elems
    float m2 = fmaxf(fmaxf(en.x, en.y), fmaxf(en.z, en.w));
    float f0 = __expf(en.x - m2), f1 = __expf(en.y - m2),
          f2 = __expf(en.z - m2), f3 = __expf(en.w - m2);
    float z2 = f0 + f1 + f2 + f3;
    float s2 = f0 * en.x + f1 * en.y + f2 * en.z + f3 * en.w;
    #pragma unroll
    for (int o = 16; o > 0; o >>= 1)
        mergeTriple(m2, z2, s2,
                    __shfl_xor_sync(0xffffffffu, m2, o),
                    __shfl_xor_sync(0xffffffffu, z2, o),
                    __shfl_xor_sync(0xffffffffu, s2, o));
    if (lane == 0) { red3[w * 3] = m2; red3[w * 3 + 1] = z2; red3[w * 3 + 2] = s2; }
    __syncthreads();
    if (tid < 32) {
        float mm = (lane < 8) ? red3[lane * 3]     : -INFINITY;
        float zz = (lane < 8) ? red3[lane * 3 + 1] : 0.f;
        float ss = (lane < 8) ? red3[lane * 3 + 2] : 0.f;
        #pragma unroll
        for (int o = 4; o > 0; o >>= 1)
            mergeTriple(mm, zz, ss,
                        __shfl_xor_sync(0xffffffffu, mm, o),
                        __shfl_xor_sync(0xffffffffu, zz, o),
                        __shfl_xor_sync(0xffffffffu, ss, o));
        if (lane == 0) g_wsum[bn] = ss / zz;
    }
}

// AV (TF32 WMMA): node_out = A @ V + wsum
__global__ void av_tf32(void) {
    __shared__ float sb[6144];
    float (*Vs)[48] = (float(*)[48])sb;
    int bh = blockIdx.y;
    int b = bh >> 3, h = bh & 7;
    int n0 = blockIdx.x * 128;
    int tid = threadIdx.x;
    const float* Ab = g_attn + ((long)b * NHh + h) * Nn * Nn;
    const float* Vb = g_qkv + (long)b * Nn * 960 + 2 * Cc + h * DHh;
    for (int idx = tid; idx < 512; idx += 256) Vs[idx >> 3][40 + (idx & 7)] = 0.f;
    int w = tid >> 5;
    wmma::fragment<wmma::accumulator, 16, 16, 8, float> c[3];
    #pragma unroll
    for (int j = 0; j < 3; j++) wmma::fill_fragment(c[j], 0.f);
    for (int m0 = 0; m0 < Nn; m0 += 64) {
        __syncthreads();
        for (int idx = tid; idx < 640; idx += 256) {
            int mm = idx / 10, c4 = (idx % 10) * 4;
            *(float4*)&Vs[mm][c4] = *(const float4*)&Vb[(long)(m0 + mm) * 960 + c4];
        }
        __syncthreads();
        #pragma unroll
        for (int kk = 0; kk < 8; kk++) {
            wmma::fragment<wmma::matrix_a, 16, 16, 8, wmma::precision::tf32, wmma::row_major> a;
            wmma::load_matrix_sync(a, &Ab[(long)(n0 + w * 16) * Nn + m0 + kk * 8], Nn);
            #pragma unroll
            for (int e = 0; e < a.num_elements; e++) a.x[e] = wmma::__float_to_tf32(a.x[e]);
            #pragma unroll
            for (int j = 0; j < 3; j++) {
                wmma::fragment<wmma::matrix_b, 16, 16, 8, wmma::precision::tf32, wmma::row_major> bf;
                wmma::load_matrix_sync(bf, &Vs[kk * 8][j * 16], 48);
                #pragma unroll
                for (int e = 0; e < bf.num_elements; e++) bf.x[e] = wmma::__float_to_tf32(bf.x[e]);
                wmma::mma_sync(c[j], a, bf, c[j]);
            }
        }
    }
    __syncthreads();
    #pragma unroll
    for (int j = 0; j < 3; j++)
        wmma::store_matrix_sync(&sb[(w * 16) * 48 + j * 16], c[j], 48, wmma::mem_row_major);
    __syncthreads();
    const float* wsp = g_wsum + b * Nn + n0;
    float* op = g_nodeout + ((long)b * Nn + n0) * Cc + h * DHh;
    #pragma unroll
    for (int i = 0; i < 5; i++) {
        int idx = tid + i * 256;
        int r = idx / 10, c4 = (idx % 10) * 4;
        float wv = wsp[r];
        float4 v = *(float4*)&sb[r * 48 + c4];
        v.x += wv; v.y += wv; v.z += wv; v.w += wv;
        *(float4*)&op[(long)r * Cc + c4] = v;
    }
}

static float* sym(const void* s) {
    void* p = nullptr;
    cudaGetSymbolAddress(&p, s);
    return (float*)p;
}

extern "C" void kernel_launch(void* const* d_in, const int* in_sizes, int n_in,
                              void* d_out, int out_size) {
    const float* x        = (const float*)d_in[0];
    const float* da_prior = (const float*)d_in[1];
    const float* qk_w     = (const float*)d_in[2];
    const float* fcp_w    = (const float*)d_in[3];
    const float* fcp_b    = (const float*)d_in[4];
    const float* ln1_g    = (const float*)d_in[5];
    const float* ln1_b    = (const float*)d_in[6];
    const float* gln_g    = (const float*)d_in[7];
    const float* gln_b    = (const float*)d_in[8];
    const float* qkv_w    = (const float*)d_in[9];
    const float* qkv_b    = (const float*)d_in[10];
    const float* proj_w   = (const float*)d_in[11];
    const float* proj_b   = (const float*)d_in[12];
    const float* exp_w    = (const float*)d_in[13];
    const float* exp_b    = (const float*)d_in[14];
    const float* red_w    = (const float*)d_in[15];
    const float* red_b    = (const float*)d_in[16];
    float* out = (float*)d_out;

    float* p_node    = sym(g_node);
    float* p_qk2     = sym(g_qk2);
    float* p_edge    = sym(g_edge);
    float* p_y       = sym(g_y);
    float* p_qkv     = sym(g_qkv);
    float* p_nodeout = sym(g_nodeout);

    transpose_in<<<dim3(32, 10, Bb), dim3(32, 32)>>>(x);
    gemm_tf32<<<dim3(10, 16, 1), 256>>>(p_node, qk_w, nullptr, p_qk2,
                                        Bb * Nn, 2 * Cc, Cc, Cc, Cc, 2 * Cc, 0, 0, 0, 1.f);
    gemm_tf32<<<dim3(16, 8, Bb), 256>>>(p_qk2, p_qk2 + Cc, nullptr, p_edge,
                                        Nn, Nn, Cc, 2 * Cc, 2 * Cc, Nn,
                                        (long)Nn * 2 * Cc, (long)Nn * 2 * Cc, (long)Nn * Nn,
                                        EDGE_SCALE);
    edge_softmax<<<Bb * Nn, 256>>>();
    fcp_kernel<<<Bb, Cc>>>(da_prior, fcp_w, fcp_b);

    for (int l = 0; l < Ll; l++) {
        norm_kernel<<<Bb * Nn, Cc>>>(ln1_g + l * Cc, ln1_b + l * Cc,
                                     gln_g + l * Cc, gln_b + l * Cc);
        gemm_tf32<<<dim3(15, 16, 1), 256>>>(p_y, qkv_w + (long)l * 3 * Cc * Cc,
                                            qkv_b + l * 3 * Cc, p_qkv,
                                            Bb * Nn, 3 * Cc, Cc, Cc, Cc, 3 * Cc, 0, 0, 0, 1.f);
        attn_score_tf32<<<dim3(16, 16, Bb * NHh), 256>>>(exp_w + l * NHh, exp_b + l * NHh);
        softmax_ednew<<<Bb * Nn, 256>>>(red_w + l * NHh, red_b + l);
        av_tf32<<<dim3(8, Bb * NHh), 256>>>();
        gemm_tf32<<<dim3(5, 16, 1), 256>>>(p_nodeout, proj_w + (long)l * Cc * Cc,
                                           proj_b + l * Cc, p_node,
                                           Bb * Nn, Cc, Cc, Cc, Cc, Cc, 0, 0, 0, 1.f);
    }
    transpose_out<<<dim3(32, 10, Bb), dim3(32, 32)>>>(out);
}